// round 4
// baseline (speedup 1.0000x reference)
#include <cuda_runtime.h>
#include <cuda_fp16.h>
#include <cstdint>

// ---------------- problem constants ----------------
#define N_ROWS 16384
#define KC 8192
#define D 256
#define LOSS_OFF 4194304
#define IDX_OFF 4194305

typedef unsigned long long u64;

// ---------------- device scratch ----------------
__device__ __half g_Ah[(size_t)N_ROWS * D];   // x fp16 [m][k]
__device__ __half g_Bh[(size_t)KC * D];       // e fp16 [n][k]
__device__ float g_Axf[(size_t)N_ROWS * D];   // x fp32 row-major (for exact recheck)
__device__ float g_en2[KC];                   // ||e||^2 fp32
__device__ float g_xn2[N_ROWS];               // ||x||^2 fp32
__device__ float g_thrpad;                    // recheck threshold pad
__device__ u64 g_part[(size_t)N_ROWS * 64];   // per row: 32 tiles x top-2
__device__ int g_idx[N_ROWS];

// ---------------- helpers ----------------
__device__ __forceinline__ uint32_t smem_u32(const void* p) {
    uint32_t a;
    asm("{ .reg .u64 t; cvta.to.shared.u64 t, %1; cvt.u32.u64 %0, t; }" : "=r"(a) : "l"(p));
    return a;
}
__device__ __forceinline__ u64 packdi(float d, int idx) {
    uint32_t u = __float_as_uint(d);
    u = (u & 0x80000000u) ? ~u : (u | 0x80000000u);
    return ((u64)u << 32) | (uint32_t)idx;
}
__device__ __forceinline__ float unpackd(u64 p) {
    uint32_t u = (uint32_t)(p >> 32);
    u = (u & 0x80000000u) ? (u ^ 0x80000000u) : ~u;
    return __uint_as_float(u);
}
__device__ __forceinline__ void cpasync16(uint32_t sdst, const void* gsrc) {
    asm volatile("cp.async.cg.shared.global [%0], [%1], 16;" :: "r"(sdst), "l"(gsrc));
}
__device__ __forceinline__ void ldmx4(uint32_t addr, uint32_t& r0, uint32_t& r1,
                                      uint32_t& r2, uint32_t& r3) {
    asm volatile("ldmatrix.sync.aligned.m8n8.x4.shared.b16 {%0,%1,%2,%3}, [%4];"
                 : "=r"(r0), "=r"(r1), "=r"(r2), "=r"(r3) : "r"(addr));
}
__device__ __forceinline__ void mma16816(float* c, const uint32_t* a, const uint32_t* b) {
    asm volatile(
        "mma.sync.aligned.m16n8k16.row.col.f32.f16.f16.f32 "
        "{%0,%1,%2,%3}, {%4,%5,%6,%7}, {%8,%9}, {%0,%1,%2,%3};"
        : "+f"(c[0]), "+f"(c[1]), "+f"(c[2]), "+f"(c[3])
        : "r"(a[0]), "r"(a[1]), "r"(a[2]), "r"(a[3]), "r"(b[0]), "r"(b[1]));
}

// ---------------- prep kernels ----------------
// enorm + init fused: grid 1024 x 256
__global__ void enorm_kernel(const float* __restrict__ E, float* out) {
    int gi = blockIdx.x * 256 + threadIdx.x;
    if (gi < N_ROWS) g_xn2[gi] = 0.0f;
    if (gi == 0) out[LOSS_OFF] = 0.0f;
    int k = blockIdx.x * 8 + (threadIdx.x >> 5);
    int lane = threadIdx.x & 31;
    const float4* p = (const float4*)(E + (size_t)k * D);
    float4 v0 = p[lane * 2], v1 = p[lane * 2 + 1];
    float s = v0.x*v0.x + v0.y*v0.y + v0.z*v0.z + v0.w*v0.w
            + v1.x*v1.x + v1.y*v1.y + v1.z*v1.z + v1.w*v1.w;
    #pragma unroll
    for (int o = 16; o > 0; o >>= 1) s += __shfl_xor_sync(0xffffffffu, s, o);
    if (lane == 0) g_en2[k] = s;
}

__global__ void prepB_kernel(const float* __restrict__ E) {
    int i = blockIdx.x * 256 + threadIdx.x;   // float4 index, 524288 total
    float4 v = *((const float4*)E + i);
    __half2 h0 = __floats2half2_rn(v.x, v.y);
    __half2 h1 = __floats2half2_rn(v.z, v.w);
    uint2 o; o.x = *(uint32_t*)&h0; o.y = *(uint32_t*)&h1;
    *((uint2*)g_Bh + i) = o;
}

// hs [b][c][hw] -> g_Ah [m][c] fp16, g_Axf [m][c] fp32, + row norms
__global__ void prepA_kernel(const float* __restrict__ hs) {
    __shared__ float tile[32][33];
    int m0 = blockIdx.x * 32, b = m0 >> 10, p0 = m0 & 1023;
    int c0 = blockIdx.y * 32;
    int tx = threadIdx.x, ty = threadIdx.y;   // 32 x 8
    float nacc = 0.0f;
    #pragma unroll
    for (int i = 0; i < 4; i++) {
        int c = c0 + ty + i * 8;
        float v = hs[((size_t)(b * 256 + c)) * 1024 + p0 + tx];
        tile[ty + i * 8][tx] = v;
        nacc = fmaf(v, v, nacc);
    }
    atomicAdd(&g_xn2[m0 + tx], nacc);
    __syncthreads();
    #pragma unroll
    for (int i = 0; i < 4; i++) {
        int row = ty + i * 8;
        float v = tile[tx][row];
        g_Ah[(size_t)(m0 + row) * D + c0 + tx] = __float2half_rn(v);
        g_Axf[(size_t)(m0 + row) * D + c0 + tx] = v;
    }
}

__global__ void bound_kernel() {
    __shared__ float sred[8];
    int tid = threadIdx.x;
    float mx = 0.0f, me = 0.0f;
    for (int i = tid; i < N_ROWS; i += 256) mx = fmaxf(mx, g_xn2[i]);
    for (int i = tid; i < KC; i += 256) me = fmaxf(me, g_en2[i]);
    #pragma unroll
    for (int o = 16; o > 0; o >>= 1) {
        mx = fmaxf(mx, __shfl_xor_sync(0xffffffffu, mx, o));
        me = fmaxf(me, __shfl_xor_sync(0xffffffffu, me, o));
    }
    if ((tid & 31) == 0) sred[tid >> 5] = mx;
    __syncthreads();
    float mxall = 0.0f;
    if (tid == 0) {
        #pragma unroll
        for (int w = 0; w < 8; w++) mxall = fmaxf(mxall, sred[w]);
    }
    __syncthreads();
    if ((tid & 31) == 0) sred[tid >> 5] = me;
    __syncthreads();
    if (tid == 0) {
        float meall = 0.0f;
        #pragma unroll
        for (int w = 0; w < 8; w++) meall = fmaxf(meall, sred[w]);
        g_thrpad = 0.006f * sqrtf(mxall) * sqrtf(meall) + 0.05f;
    }
}

// ---------------- main GEMM (fp16 mma.sync), CTA 128x256, 512 threads ----------------
#define SA_OFF(b) ((b) * 16384)
#define SB_OFF(b) (32768 + (b) * 32768)
#define SEN_OFF   98304
#define SPART_OFF 99328
#define SMEM_SZ   (1024 + 98304 + 1024 + 8192)

__global__ void __launch_bounds__(512, 1)
gemm_kernel() {
    extern __shared__ char smem_raw[];
    char* base = (char*)(((uintptr_t)smem_raw + 1023) & ~(uintptr_t)1023);
    uint32_t sb = smem_u32(base);
    float* sEn = (float*)(base + SEN_OFF);
    u64* sPart = (u64*)(base + SPART_OFF);

    const int tid = threadIdx.x;
    const int lane = tid & 31, wid = tid >> 5;
    const int wm = wid & 3, wn = wid >> 2;          // 4M x 4N warps
    const int ntile = blockIdx.x, mtile = blockIdx.y;
    const int m0 = mtile * 128, n0 = ntile * 256;

    if (tid < 256) sEn[tid] = g_en2[n0 + tid];

    auto load_chunk = [&](int c, int bf) {
        #pragma unroll
        for (int it = 0; it < 2; it++) {          // A: 1024 groups of 16B
            int idx = tid + it * 512;
            int row = idx >> 3, kg = idx & 7;
            uint32_t soff = row * 128 + (((uint32_t)(kg ^ (row & 7))) << 4);
            cpasync16(sb + SA_OFF(bf) + soff,
                      g_Ah + (size_t)(m0 + row) * D + c * 64 + kg * 8);
        }
        #pragma unroll
        for (int it = 0; it < 4; it++) {          // B: 2048 groups of 16B
            int idx = tid + it * 512;
            int row = idx >> 3, kg = idx & 7;
            uint32_t soff = row * 128 + (((uint32_t)(kg ^ (row & 7))) << 4);
            cpasync16(sb + SB_OFF(bf) + soff,
                      g_Bh + (size_t)(n0 + row) * D + c * 64 + kg * 8);
        }
        asm volatile("cp.async.commit_group;");
    };

    float acc[2][8][4];
    #pragma unroll
    for (int mt = 0; mt < 2; mt++)
        #pragma unroll
        for (int nt = 0; nt < 8; nt++)
            #pragma unroll
            for (int q = 0; q < 4; q++) acc[mt][nt][q] = 0.0f;

    load_chunk(0, 0);

    for (int c = 0; c < 4; c++) {
        if (c + 1 < 4) {
            load_chunk(c + 1, (c + 1) & 1);
            asm volatile("cp.async.wait_group 1;" ::: "memory");
        } else {
            asm volatile("cp.async.wait_group 0;" ::: "memory");
        }
        __syncthreads();
        uint32_t ab = sb + SA_OFF(c & 1), bbse = sb + SB_OFF(c & 1);
        #pragma unroll
        for (int ks = 0; ks < 4; ks++) {
            uint32_t a[2][4], bb[8][2];
            uint32_t kg = ks * 2 + (lane >> 4);
            uint32_t kx = ((kg ^ (lane & 7)) << 4);
            #pragma unroll
            for (int mt = 0; mt < 2; mt++) {
                uint32_t row = wm * 32 + mt * 16 + (lane & 15);
                ldmx4(ab + row * 128 + kx, a[mt][0], a[mt][1], a[mt][2], a[mt][3]);
            }
            #pragma unroll
            for (int nt2 = 0; nt2 < 4; nt2++) {
                uint32_t row = wn * 64 + nt2 * 16 + (lane & 15);
                uint32_t r0, r1, r2, r3;
                ldmx4(bbse + row * 128 + kx, r0, r1, r2, r3);
                bb[nt2 * 2][0] = r0; bb[nt2 * 2][1] = r2;
                bb[nt2 * 2 + 1][0] = r1; bb[nt2 * 2 + 1][1] = r3;
            }
            #pragma unroll
            for (int mt = 0; mt < 2; mt++)
                #pragma unroll
                for (int nt = 0; nt < 8; nt++)
                    mma16816(acc[mt][nt], a[mt], bb[nt]);
        }
        __syncthreads();
    }

    // epilogue: per-row top-2 within this warp's 64-col strip, then merge 4 strips
    #pragma unroll
    for (int mt = 0; mt < 2; mt++) {
        #pragma unroll
        for (int half = 0; half < 2; half++) {
            u64 t1 = ~0ull, t2 = ~0ull;
            #pragma unroll
            for (int nt = 0; nt < 8; nt++) {
                #pragma unroll
                for (int cc = 0; cc < 2; cc++) {
                    int col = wn * 64 + nt * 8 + (lane & 3) * 2 + cc;
                    float dist = fmaf(-2.0f, acc[mt][nt][half * 2 + cc], sEn[col]);
                    u64 pk = packdi(dist, n0 + col);
                    if (pk < t1) { t2 = t1; t1 = pk; }
                    else if (pk < t2) { t2 = pk; }
                }
            }
            #pragma unroll
            for (int dlt = 1; dlt <= 2; dlt <<= 1) {
                u64 o1 = __shfl_xor_sync(0xffffffffu, t1, dlt);
                u64 o2 = __shfl_xor_sync(0xffffffffu, t2, dlt);
                u64 n1 = min(t1, o1);
                u64 n2 = min(max(t1, o1), min(t2, o2));
                t1 = n1; t2 = n2;
            }
            if ((lane & 3) == 0) {
                int rl = wm * 32 + mt * 16 + half * 8 + (lane >> 2);
                sPart[rl * 8 + wn * 2] = t1;
                sPart[rl * 8 + wn * 2 + 1] = t2;
            }
        }
    }
    __syncthreads();
    if (tid < 128) {
        u64 p1 = ~0ull, p2 = ~0ull;
        #pragma unroll
        for (int w = 0; w < 4; w++) {
            u64 a1 = sPart[tid * 8 + w * 2], a2 = sPart[tid * 8 + w * 2 + 1];
            u64 n1 = min(p1, a1);
            u64 n2 = min(max(p1, a1), min(p2, a2));
            p1 = n1; p2 = n2;
        }
        g_part[(size_t)(m0 + tid) * 64 + ntile * 2] = p1;
        g_part[(size_t)(m0 + tid) * 64 + ntile * 2 + 1] = p2;
    }
}

// ---------------- merge + exact recheck ----------------
__device__ __forceinline__ u64 exact_pk(const float* __restrict__ E,
                                        const float xv[8], int lane, int k) {
    const float* ek = E + (size_t)k * D;
    float s = 0.0f;
    #pragma unroll
    for (int j = 0; j < 8; j++) s = fmaf(xv[j], __ldg(ek + lane + j * 32), s);
    #pragma unroll
    for (int o = 16; o > 0; o >>= 1) s += __shfl_xor_sync(0xffffffffu, s, o);
    float dist = fmaf(-2.0f, s, __ldg(&g_en2[k]));
    return packdi(dist, k);
}

__global__ void merge_kernel(const float* __restrict__ E, float* __restrict__ out) {
    int wid = threadIdx.x >> 5, lane = threadIdx.x & 31;
    int row = blockIdx.x * 8 + wid;
    const float* xr = g_Axf + (size_t)row * D;
    float xv[8];
    #pragma unroll
    for (int j = 0; j < 8; j++) xv[j] = __ldg(xr + lane + j * 32);   // coalesced

    u64 e1 = g_part[(size_t)row * 64 + lane * 2];
    u64 e2 = g_part[(size_t)row * 64 + lane * 2 + 1];

    u64 m = e1;
    #pragma unroll
    for (int o = 16; o > 0; o >>= 1) m = min(m, __shfl_xor_sync(0xffffffffu, m, o));
    float thr = unpackd(m) + g_thrpad;

    u64 best = ~0ull;
    bool full = (unpackd(e2) <= thr);
    bool single = (!full) && (unpackd(e1) <= thr);
    int myidx = (int)(e1 & 0xFFFFFFFFu);
    unsigned msing = __ballot_sync(0xffffffffu, single);
    unsigned mfull = __ballot_sync(0xffffffffu, full);
    while (msing) {
        int src = __ffs(msing) - 1; msing &= msing - 1;
        int k = __shfl_sync(0xffffffffu, myidx, src);
        best = min(best, exact_pk(E, xv, lane, k));
    }
    while (mfull) {
        int src = __ffs(mfull) - 1; mfull &= mfull - 1;
        int k0 = src * 256;
        for (int k = k0; k < k0 + 256; k++)
            best = min(best, exact_pk(E, xv, lane, k));
    }
    if (lane == 0) {
        int k = (int)(best & 0xFFFFFFFFu);
        g_idx[row] = k;
        out[IDX_OFF + row] = (float)k;
    }
}

// ---------------- final gather + loss ----------------
__global__ void final_kernel(const float* __restrict__ hs,
                             const float* __restrict__ E,
                             float* __restrict__ out) {
    __shared__ int sIdx[128];
    __shared__ float sRed[8];
    int tid = threadIdx.x;
    int row0 = blockIdx.x * 128;
    int b = row0 >> 10, p0 = row0 & 1023;
    size_t xbase = (size_t)b * 256 * 1024 + p0;

    if (tid < 128) sIdx[tid] = g_idx[row0 + tid];
    __syncthreads();

    float lsum = 0.0f;
    #pragma unroll 4
    for (int i = 0; i < 128; i++) {
        int lin = i * 256 + tid;
        int c = lin >> 7, r = lin & 127;
        int k = sIdx[r];
        float ev = __ldg(E + (size_t)k * D + c);
        size_t ad = xbase + (size_t)c * 1024 + r;
        float xv = hs[ad];
        out[ad] = ev;
        float dlt = ev - xv;
        lsum = fmaf(dlt, dlt, lsum);
    }
    #pragma unroll
    for (int o = 16; o > 0; o >>= 1) lsum += __shfl_xor_sync(0xffffffffu, lsum, o);
    if ((tid & 31) == 0) sRed[tid >> 5] = lsum;
    __syncthreads();
    if (tid == 0) {
        float tot = 0.0f;
        #pragma unroll
        for (int w = 0; w < 8; w++) tot += sRed[w];
        atomicAdd(out + LOSS_OFF, tot * (1.25f / 4194304.0f));
    }
}

extern "C" void kernel_launch(void* const* d_in, const int* in_sizes, int n_in,
                              void* d_out, int out_size) {
    const float* hs = (const float*)d_in[0];
    const float* E  = (const float*)d_in[1];
    float* out = (float*)d_out;

    cudaFuncSetAttribute(gemm_kernel,
                         cudaFuncAttributeMaxDynamicSharedMemorySize, SMEM_SZ);

    enorm_kernel<<<KC / 8, 256>>>(E, out);
    prepB_kernel<<<(KC * D / 4) / 256, 256>>>(E);
    prepA_kernel<<<dim3(N_ROWS / 32, D / 32), dim3(32, 8)>>>(hs);
    bound_kernel<<<1, 256>>>();
    gemm_kernel<<<dim3(KC / 256, N_ROWS / 128), 512, SMEM_SZ>>>();
    merge_kernel<<<N_ROWS / 8, 256>>>(E, out);
    final_kernel<<<N_ROWS / 128, 256>>>(hs, E, out);
}

// round 5
// speedup vs baseline: 1.1145x; 1.1145x over previous
#include <cuda_runtime.h>
#include <cuda_fp16.h>
#include <cstdint>

// ---------------- problem constants ----------------
#define N_ROWS 16384
#define KC 8192
#define D 256
#define LOSS_OFF 4194304
#define IDX_OFF 4194305

typedef unsigned long long u64;

// ---------------- device scratch ----------------
__device__ __half g_Ah[(size_t)N_ROWS * D];   // x fp16 [m][k]
__device__ __half g_Bh[(size_t)KC * D];       // e fp16 [n][k]
__device__ float g_Axf[(size_t)N_ROWS * D];   // x fp32 row-major (exact recheck)
__device__ float g_en2[KC];                   // ||e||^2 fp32
__device__ int g_maxxn = 0;                   // max ||x||^2 bits (atomicMax, idempotent)
__device__ int g_maxen = 0;                   // max ||e||^2 bits
__device__ u64 g_part[(size_t)N_ROWS * 128];  // per row: 64 tiles x top-2
__device__ int g_idx[N_ROWS];

// ---------------- helpers ----------------
__device__ __forceinline__ uint32_t smem_u32(const void* p) {
    uint32_t a;
    asm("{ .reg .u64 t; cvta.to.shared.u64 t, %1; cvt.u32.u64 %0, t; }" : "=r"(a) : "l"(p));
    return a;
}
__device__ __forceinline__ u64 packdi(float d, int idx) {
    uint32_t u = __float_as_uint(d);
    u = (u & 0x80000000u) ? ~u : (u | 0x80000000u);
    return ((u64)u << 32) | (uint32_t)idx;
}
__device__ __forceinline__ float unpackd(u64 p) {
    uint32_t u = (uint32_t)(p >> 32);
    u = (u & 0x80000000u) ? (u ^ 0x80000000u) : ~u;
    return __uint_as_float(u);
}
__device__ __forceinline__ void cpasync16(uint32_t sdst, const void* gsrc) {
    asm volatile("cp.async.cg.shared.global [%0], [%1], 16;" :: "r"(sdst), "l"(gsrc));
}
__device__ __forceinline__ void ldmx4(uint32_t addr, uint32_t& r0, uint32_t& r1,
                                      uint32_t& r2, uint32_t& r3) {
    asm volatile("ldmatrix.sync.aligned.m8n8.x4.shared.b16 {%0,%1,%2,%3}, [%4];"
                 : "=r"(r0), "=r"(r1), "=r"(r2), "=r"(r3) : "r"(addr));
}
__device__ __forceinline__ void mma16816(float* c, const uint32_t* a, const uint32_t* b) {
    asm volatile(
        "mma.sync.aligned.m16n8k16.row.col.f32.f16.f16.f32 "
        "{%0,%1,%2,%3}, {%4,%5,%6,%7}, {%8,%9}, {%0,%1,%2,%3};"
        : "+f"(c[0]), "+f"(c[1]), "+f"(c[2]), "+f"(c[3])
        : "r"(a[0]), "r"(a[1]), "r"(a[2]), "r"(a[3]), "r"(b[0]), "r"(b[1]));
}

// ---------------- prepE: E -> fp16 + ||e||^2 + max norm + loss init ----------------
__global__ void prepE_kernel(const float* __restrict__ E, float* out) {
    int k = blockIdx.x * 8 + (threadIdx.x >> 5);
    int lane = threadIdx.x & 31;
    if (blockIdx.x == 0 && threadIdx.x == 0) out[LOSS_OFF] = 0.0f;
    const float4* p = (const float4*)(E + (size_t)k * D);
    float4 v0 = p[lane * 2], v1 = p[lane * 2 + 1];
    __half2 h0 = __floats2half2_rn(v0.x, v0.y), h1 = __floats2half2_rn(v0.z, v0.w);
    __half2 h2 = __floats2half2_rn(v1.x, v1.y), h3 = __floats2half2_rn(v1.z, v1.w);
    uint4 o;
    o.x = *(uint32_t*)&h0; o.y = *(uint32_t*)&h1;
    o.z = *(uint32_t*)&h2; o.w = *(uint32_t*)&h3;
    *(uint4*)(g_Bh + (size_t)k * D + lane * 8) = o;
    float s = v0.x*v0.x + v0.y*v0.y + v0.z*v0.z + v0.w*v0.w
            + v1.x*v1.x + v1.y*v1.y + v1.z*v1.z + v1.w*v1.w;
    #pragma unroll
    for (int off = 16; off > 0; off >>= 1) s += __shfl_xor_sync(0xffffffffu, s, off);
    if (lane == 0) {
        g_en2[k] = s;
        atomicMax(&g_maxen, __float_as_int(s));
    }
}

// ---------------- prepA: hs -> g_Ah fp16 + g_Axf fp32 (transposed), max row norm ----
__global__ void prepA_kernel(const float* __restrict__ hs) {
    __shared__ float tile[32][33];
    __shared__ float snorm[8][32];
    int m0 = blockIdx.x * 32, b = m0 >> 10, p0 = m0 & 1023;
    int tx = threadIdx.x, ty = threadIdx.y;   // 32 x 8
    float nacc = 0.0f;
    for (int cc = 0; cc < 8; cc++) {
        int c0 = cc * 32;
        __syncthreads();
        #pragma unroll
        for (int i = 0; i < 4; i++) {
            int c = c0 + ty + i * 8;
            float v = hs[((size_t)(b * 256 + c)) * 1024 + p0 + tx];
            tile[ty + i * 8][tx] = v;
            nacc = fmaf(v, v, nacc);            // row m0+tx partial
        }
        __syncthreads();
        #pragma unroll
        for (int i = 0; i < 4; i++) {
            int row = ty + i * 8;
            float v = tile[tx][row];
            g_Ah[(size_t)(m0 + row) * D + c0 + tx] = __float2half_rn(v);
            g_Axf[(size_t)(m0 + row) * D + c0 + tx] = v;
        }
    }
    snorm[ty][tx] = nacc;
    __syncthreads();
    if (ty == 0) {
        float tot = 0.0f;
        #pragma unroll
        for (int j = 0; j < 8; j++) tot += snorm[j][tx];
        #pragma unroll
        for (int off = 16; off > 0; off >>= 1)
            tot = fmaxf(tot, __shfl_xor_sync(0xffffffffu, tot, off));
        if (tx == 0) atomicMax(&g_maxxn, __float_as_int(tot));
    }
}

// ---------------- main GEMM (fp16 mma.sync), CTA 128x128, 3-stage pipeline --------
#define STG_A(s) ((s) * 32768)
#define STG_B(s) ((s) * 32768 + 16384)
#define SEN_OFF   98304
#define SPART_OFF 98816
#define SMEM_SZ   (1024 + 98816 + 4096)

__global__ void __launch_bounds__(256, 2)
gemm_kernel() {
    extern __shared__ char smem_raw[];
    char* base = (char*)(((uintptr_t)smem_raw + 1023) & ~(uintptr_t)1023);
    uint32_t sb = smem_u32(base);
    float* sEn = (float*)(base + SEN_OFF);
    u64* sPart = (u64*)(base + SPART_OFF);

    const int tid = threadIdx.x;
    const int lane = tid & 31, wid = tid >> 5;
    const int wm = wid & 3, wn = wid >> 2;          // 4M x 2N warps
    const int ntile = blockIdx.x, mtile = blockIdx.y;
    const int m0 = mtile * 128, n0 = ntile * 128;

    if (tid < 128) sEn[tid] = g_en2[n0 + tid];

    auto load_chunk = [&](int c, int s) {
        #pragma unroll
        for (int it = 0; it < 4; it++) {
            int idx = tid + it * 256;
            int row = idx >> 3, kg = idx & 7;
            uint32_t soff = row * 128 + (((uint32_t)(kg ^ (row & 7))) << 4);
            cpasync16(sb + STG_A(s) + soff,
                      g_Ah + (size_t)(m0 + row) * D + c * 64 + kg * 8);
            cpasync16(sb + STG_B(s) + soff,
                      g_Bh + (size_t)(n0 + row) * D + c * 64 + kg * 8);
        }
        asm volatile("cp.async.commit_group;");
    };

    float acc[2][8][4];
    #pragma unroll
    for (int mt = 0; mt < 2; mt++)
        #pragma unroll
        for (int nt = 0; nt < 8; nt++)
            #pragma unroll
            for (int q = 0; q < 4; q++) acc[mt][nt][q] = 0.0f;

    load_chunk(0, 0);
    load_chunk(1, 1);

    #pragma unroll
    for (int c = 0; c < 4; c++) {
        if (c + 2 < 4) load_chunk(c + 2, (c + 2) % 3);
        if (c == 0 || c == 1) asm volatile("cp.async.wait_group 2;" ::: "memory");
        else if (c == 2)      asm volatile("cp.async.wait_group 1;" ::: "memory");
        else                  asm volatile("cp.async.wait_group 0;" ::: "memory");
        __syncthreads();
        uint32_t ab = sb + STG_A(c % 3), bbse = sb + STG_B(c % 3);
        #pragma unroll
        for (int ks = 0; ks < 4; ks++) {
            uint32_t a[2][4], bb[8][2];
            uint32_t kg = ks * 2 + (lane >> 4);
            uint32_t kx = ((kg ^ (lane & 7)) << 4);
            #pragma unroll
            for (int mt = 0; mt < 2; mt++) {
                uint32_t row = wm * 32 + mt * 16 + (lane & 15);
                ldmx4(ab + row * 128 + kx, a[mt][0], a[mt][1], a[mt][2], a[mt][3]);
            }
            #pragma unroll
            for (int nt2 = 0; nt2 < 4; nt2++) {
                uint32_t row = wn * 64 + nt2 * 16 + (lane & 15);
                uint32_t r0, r1, r2, r3;
                ldmx4(bbse + row * 128 + kx, r0, r1, r2, r3);
                bb[nt2 * 2][0] = r0; bb[nt2 * 2][1] = r2;
                bb[nt2 * 2 + 1][0] = r1; bb[nt2 * 2 + 1][1] = r3;
            }
            #pragma unroll
            for (int mt = 0; mt < 2; mt++)
                #pragma unroll
                for (int nt = 0; nt < 8; nt++)
                    mma16816(acc[mt][nt], a[mt], bb[nt]);
        }
        __syncthreads();
    }

    // epilogue: per-row top-2 of dist = en2 - 2*dot within this 128-col tile
    #pragma unroll
    for (int mt = 0; mt < 2; mt++) {
        #pragma unroll
        for (int half = 0; half < 2; half++) {
            u64 t1 = ~0ull, t2 = ~0ull;
            #pragma unroll
            for (int nt = 0; nt < 8; nt++) {
                #pragma unroll
                for (int cc = 0; cc < 2; cc++) {
                    int col = wn * 64 + nt * 8 + (lane & 3) * 2 + cc;
                    float dist = fmaf(-2.0f, acc[mt][nt][half * 2 + cc], sEn[col]);
                    u64 pk = packdi(dist, n0 + col);
                    if (pk < t1) { t2 = t1; t1 = pk; }
                    else if (pk < t2) { t2 = pk; }
                }
            }
            #pragma unroll
            for (int dlt = 1; dlt <= 2; dlt <<= 1) {
                u64 o1 = __shfl_xor_sync(0xffffffffu, t1, dlt);
                u64 o2 = __shfl_xor_sync(0xffffffffu, t2, dlt);
                u64 n1 = min(t1, o1);
                u64 n2 = min(max(t1, o1), min(t2, o2));
                t1 = n1; t2 = n2;
            }
            if ((lane & 3) == 0) {
                int rl = wm * 32 + mt * 16 + half * 8 + (lane >> 2);
                sPart[rl * 4 + wn * 2] = t1;
                sPart[rl * 4 + wn * 2 + 1] = t2;
            }
        }
    }
    __syncthreads();
    if (tid < 128) {
        u64 a1 = sPart[tid * 4], a2 = sPart[tid * 4 + 1];
        u64 b1 = sPart[tid * 4 + 2], b2 = sPart[tid * 4 + 3];
        u64 n1 = min(a1, b1);
        u64 n2 = min(max(a1, b1), min(a2, b2));
        g_part[(size_t)(m0 + tid) * 128 + ntile * 2] = n1;
        g_part[(size_t)(m0 + tid) * 128 + ntile * 2 + 1] = n2;
    }
}

// ---------------- merge + exact recheck ----------------
__device__ __forceinline__ u64 exact_pk(const float* __restrict__ E,
                                        const float xv[8], int lane, int k) {
    const float* ek = E + (size_t)k * D;
    float s = 0.0f;
    #pragma unroll
    for (int j = 0; j < 8; j++) s = fmaf(xv[j], __ldg(ek + lane + j * 32), s);
    #pragma unroll
    for (int o = 16; o > 0; o >>= 1) s += __shfl_xor_sync(0xffffffffu, s, o);
    float dist = fmaf(-2.0f, s, __ldg(&g_en2[k]));
    return packdi(dist, k);
}

__global__ void merge_kernel(const float* __restrict__ E, float* __restrict__ out) {
    int wid = threadIdx.x >> 5, lane = threadIdx.x & 31;
    int row = blockIdx.x * 8 + wid;
    const float* xr = g_Axf + (size_t)row * D;
    float xv[8];
    #pragma unroll
    for (int j = 0; j < 8; j++) xv[j] = __ldg(xr + lane + j * 32);   // coalesced

    u64 e[4];
    #pragma unroll
    for (int j = 0; j < 4; j++) e[j] = g_part[(size_t)row * 128 + lane * 4 + j];

    u64 m = min(min(e[0], e[1]), min(e[2], e[3]));
    #pragma unroll
    for (int o = 16; o > 0; o >>= 1) m = min(m, __shfl_xor_sync(0xffffffffu, m, o));
    float pad = 0.006f * sqrtf(__int_as_float(g_maxxn))
                       * sqrtf(__int_as_float(g_maxen)) + 0.05f;
    float thr = unpackd(m) + pad;

    u64 best = ~0ull;
    #pragma unroll
    for (int t = 0; t < 2; t++) {
        float f1 = unpackd(e[2 * t]);
        float f2 = unpackd(e[2 * t + 1]);
        bool full = (f2 <= thr);
        bool single = (!full) && (f1 <= thr);
        int myidx = (int)(e[2 * t] & 0xFFFFFFFFu);
        unsigned msing = __ballot_sync(0xffffffffu, single);
        unsigned mfull = __ballot_sync(0xffffffffu, full);
        while (msing) {
            int src = __ffs(msing) - 1; msing &= msing - 1;
            int k = __shfl_sync(0xffffffffu, myidx, src);
            best = min(best, exact_pk(E, xv, lane, k));
        }
        while (mfull) {
            int src = __ffs(mfull) - 1; mfull &= mfull - 1;
            int k0 = (src * 2 + t) * 128;
            for (int k = k0; k < k0 + 128; k++)
                best = min(best, exact_pk(E, xv, lane, k));
        }
    }
    if (lane == 0) {
        int k = (int)(best & 0xFFFFFFFFu);
        g_idx[row] = k;
        out[IDX_OFF + row] = (float)k;
    }
}

// ---------------- final gather + loss ----------------
__global__ void final_kernel(const float* __restrict__ hs,
                             const float* __restrict__ E,
                             float* __restrict__ out) {
    __shared__ int sIdx[128];
    __shared__ float sRed[8];
    int tid = threadIdx.x;
    int row0 = blockIdx.x * 128;
    int b = row0 >> 10, p0 = row0 & 1023;
    size_t xbase = (size_t)b * 256 * 1024 + p0;

    if (tid < 128) sIdx[tid] = g_idx[row0 + tid];
    __syncthreads();

    float lsum = 0.0f;
    #pragma unroll 4
    for (int i = 0; i < 128; i++) {
        int lin = i * 256 + tid;
        int c = lin >> 7, r = lin & 127;
        int k = sIdx[r];
        float ev = __ldg(E + (size_t)k * D + c);
        size_t ad = xbase + (size_t)c * 1024 + r;
        float xv = hs[ad];
        out[ad] = ev;
        float dlt = ev - xv;
        lsum = fmaf(dlt, dlt, lsum);
    }
    #pragma unroll
    for (int o = 16; o > 0; o >>= 1) lsum += __shfl_xor_sync(0xffffffffu, lsum, o);
    if ((tid & 31) == 0) sRed[tid >> 5] = lsum;
    __syncthreads();
    if (tid == 0) {
        float tot = 0.0f;
        #pragma unroll
        for (int w = 0; w < 8; w++) tot += sRed[w];
        atomicAdd(out + LOSS_OFF, tot * (1.25f / 4194304.0f));
    }
}

extern "C" void kernel_launch(void* const* d_in, const int* in_sizes, int n_in,
                              void* d_out, int out_size) {
    const float* hs = (const float*)d_in[0];
    const float* E  = (const float*)d_in[1];
    float* out = (float*)d_out;

    cudaFuncSetAttribute(gemm_kernel,
                         cudaFuncAttributeMaxDynamicSharedMemorySize, SMEM_SZ);

    prepE_kernel<<<KC / 8, 256>>>(E, out);
    prepA_kernel<<<N_ROWS / 32, dim3(32, 8)>>>(hs);
    gemm_kernel<<<dim3(KC / 128, N_ROWS / 128), 256, SMEM_SZ>>>();
    merge_kernel<<<N_ROWS / 8, 256>>>(E, out);
    final_kernel<<<N_ROWS / 128, 256>>>(hs, E, out);
}

// round 6
// speedup vs baseline: 1.5752x; 1.4134x over previous
#include <cuda_runtime.h>
#include <cuda_fp16.h>
#include <cstdint>

// ---------------- problem constants ----------------
#define N_ROWS 16384
#define KC 8192
#define D 256
#define LOSS_OFF 4194304
#define IDX_OFF 4194305

typedef unsigned long long u64;

// ---------------- device scratch ----------------
__device__ __half g_Ah[(size_t)N_ROWS * D];   // x fp16 [m][k]
__device__ __half g_Bh[(size_t)KC * D];       // e fp16 [n][k]
__device__ float g_Axf[(size_t)N_ROWS * D];   // x fp32 row-major (exact recheck)
__device__ float g_en2[KC];                   // ||e||^2 fp32
__device__ int g_maxxn = 0;                   // max ||x||^2 bits (atomicMax, idempotent)
__device__ int g_maxen = 0;                   // max ||e||^2 bits
__device__ u64 g_part[(size_t)N_ROWS * 128];  // per row: 64 tiles x top-2
__device__ int g_idx[N_ROWS];

// ---------------- helpers ----------------
__device__ __forceinline__ uint32_t smem_u32(const void* p) {
    uint32_t a;
    asm("{ .reg .u64 t; cvta.to.shared.u64 t, %1; cvt.u32.u64 %0, t; }" : "=r"(a) : "l"(p));
    return a;
}
__device__ __forceinline__ u64 packdi(float d, int idx) {
    uint32_t u = __float_as_uint(d);
    u = (u & 0x80000000u) ? ~u : (u | 0x80000000u);
    return ((u64)u << 32) | (uint32_t)idx;
}
__device__ __forceinline__ float unpackd(u64 p) {
    uint32_t u = (uint32_t)(p >> 32);
    u = (u & 0x80000000u) ? (u ^ 0x80000000u) : ~u;
    return __uint_as_float(u);
}
__device__ __forceinline__ void cpasync16(uint32_t sdst, const void* gsrc) {
    asm volatile("cp.async.cg.shared.global [%0], [%1], 16;" :: "r"(sdst), "l"(gsrc));
}
__device__ __forceinline__ void ldmx4(uint32_t addr, uint32_t& r0, uint32_t& r1,
                                      uint32_t& r2, uint32_t& r3) {
    asm volatile("ldmatrix.sync.aligned.m8n8.x4.shared.b16 {%0,%1,%2,%3}, [%4];"
                 : "=r"(r0), "=r"(r1), "=r"(r2), "=r"(r3) : "r"(addr));
}
__device__ __forceinline__ void mma16816(float* c, const uint32_t* a, const uint32_t* b) {
    asm volatile(
        "mma.sync.aligned.m16n8k16.row.col.f32.f16.f16.f32 "
        "{%0,%1,%2,%3}, {%4,%5,%6,%7}, {%8,%9}, {%0,%1,%2,%3};"
        : "+f"(c[0]), "+f"(c[1]), "+f"(c[2]), "+f"(c[3])
        : "r"(a[0]), "r"(a[1]), "r"(a[2]), "r"(a[3]), "r"(b[0]), "r"(b[1]));
}

// ---------------- prepE: E -> fp16 + ||e||^2 + max norm + loss init ----------------
__global__ void prepE_kernel(const float* __restrict__ E, float* out) {
    int k = blockIdx.x * 8 + (threadIdx.x >> 5);
    int lane = threadIdx.x & 31;
    if (blockIdx.x == 0 && threadIdx.x == 0) out[LOSS_OFF] = 0.0f;
    const float4* p = (const float4*)(E + (size_t)k * D);
    float4 v0 = p[lane * 2], v1 = p[lane * 2 + 1];
    __half2 h0 = __floats2half2_rn(v0.x, v0.y), h1 = __floats2half2_rn(v0.z, v0.w);
    __half2 h2 = __floats2half2_rn(v1.x, v1.y), h3 = __floats2half2_rn(v1.z, v1.w);
    uint4 o;
    o.x = *(uint32_t*)&h0; o.y = *(uint32_t*)&h1;
    o.z = *(uint32_t*)&h2; o.w = *(uint32_t*)&h3;
    *(uint4*)(g_Bh + (size_t)k * D + lane * 8) = o;
    float s = v0.x*v0.x + v0.y*v0.y + v0.z*v0.z + v0.w*v0.w
            + v1.x*v1.x + v1.y*v1.y + v1.z*v1.z + v1.w*v1.w;
    #pragma unroll
    for (int off = 16; off > 0; off >>= 1) s += __shfl_xor_sync(0xffffffffu, s, off);
    if (lane == 0) {
        g_en2[k] = s;
        atomicMax(&g_maxen, __float_as_int(s));
    }
}

// ---------------- prepA: hs -> g_Ah fp16 + g_Axf fp32 (transposed), max row norm ----
__global__ void prepA_kernel(const float* __restrict__ hs) {
    __shared__ float tile[32][33];
    __shared__ float snorm[8][32];
    int m0 = blockIdx.x * 32, b = m0 >> 10, p0 = m0 & 1023;
    int tx = threadIdx.x, ty = threadIdx.y;   // 32 x 8
    float nacc = 0.0f;
    for (int cc = 0; cc < 8; cc++) {
        int c0 = cc * 32;
        __syncthreads();
        #pragma unroll
        for (int i = 0; i < 4; i++) {
            int c = c0 + ty + i * 8;
            float v = hs[((size_t)(b * 256 + c)) * 1024 + p0 + tx];
            tile[ty + i * 8][tx] = v;
            nacc = fmaf(v, v, nacc);
        }
        __syncthreads();
        #pragma unroll
        for (int i = 0; i < 4; i++) {
            int row = ty + i * 8;
            float v = tile[tx][row];
            g_Ah[(size_t)(m0 + row) * D + c0 + tx] = __float2half_rn(v);
            g_Axf[(size_t)(m0 + row) * D + c0 + tx] = v;
        }
    }
    snorm[ty][tx] = nacc;
    __syncthreads();
    if (ty == 0) {
        float tot = 0.0f;
        #pragma unroll
        for (int j = 0; j < 8; j++) tot += snorm[j][tx];
        #pragma unroll
        for (int off = 16; off > 0; off >>= 1)
            tot = fmaxf(tot, __shfl_xor_sync(0xffffffffu, tot, off));
        if (tx == 0) atomicMax(&g_maxxn, __float_as_int(tot));
    }
}

// ---------------- main GEMM (fp16 mma.sync), CTA 128x128, 2-stage (R3 config) ------
#define SA_OFF(b) ((b) * 16384)
#define SB_OFF(b) (32768 + (b) * 16384)
#define SEN_OFF   65536
#define SPART_OFF 66048
#define SMEM_SZ   (1024 + 66048 + 4096)

__global__ void __launch_bounds__(256, 2)
gemm_kernel() {
    extern __shared__ char smem_raw[];
    char* base = (char*)(((uintptr_t)smem_raw + 1023) & ~(uintptr_t)1023);
    uint32_t sb = smem_u32(base);
    float* sEn = (float*)(base + SEN_OFF);
    u64* sPart = (u64*)(base + SPART_OFF);

    const int tid = threadIdx.x;
    const int lane = tid & 31, wid = tid >> 5;
    const int wm = wid & 3, wn = wid >> 2;
    const int ntile = blockIdx.x, mtile = blockIdx.y;
    const int m0 = mtile * 128, n0 = ntile * 128;

    if (tid < 128) sEn[tid] = g_en2[n0 + tid];

    auto load_chunk = [&](int c, int bf) {
        #pragma unroll
        for (int it = 0; it < 4; it++) {
            int idx = tid + it * 256;
            int row = idx >> 3, kg = idx & 7;
            uint32_t soff = row * 128 + (((uint32_t)(kg ^ (row & 7))) << 4);
            cpasync16(sb + SA_OFF(bf) + soff,
                      g_Ah + (size_t)(m0 + row) * D + c * 64 + kg * 8);
            cpasync16(sb + SB_OFF(bf) + soff,
                      g_Bh + (size_t)(n0 + row) * D + c * 64 + kg * 8);
        }
        asm volatile("cp.async.commit_group;");
    };

    float acc[2][8][4];
    #pragma unroll
    for (int mt = 0; mt < 2; mt++)
        #pragma unroll
        for (int nt = 0; nt < 8; nt++)
            #pragma unroll
            for (int q = 0; q < 4; q++) acc[mt][nt][q] = 0.0f;

    load_chunk(0, 0);

    for (int c = 0; c < 4; c++) {
        if (c + 1 < 4) {
            load_chunk(c + 1, (c + 1) & 1);
            asm volatile("cp.async.wait_group 1;" ::: "memory");
        } else {
            asm volatile("cp.async.wait_group 0;" ::: "memory");
        }
        __syncthreads();
        uint32_t ab = sb + SA_OFF(c & 1), bbse = sb + SB_OFF(c & 1);
        #pragma unroll
        for (int ks = 0; ks < 4; ks++) {
            uint32_t a[2][4], bb[8][2];
            uint32_t kg = ks * 2 + (lane >> 4);
            uint32_t kx = ((kg ^ (lane & 7)) << 4);
            #pragma unroll
            for (int mt = 0; mt < 2; mt++) {
                uint32_t row = wm * 32 + mt * 16 + (lane & 15);
                ldmx4(ab + row * 128 + kx, a[mt][0], a[mt][1], a[mt][2], a[mt][3]);
            }
            #pragma unroll
            for (int nt2 = 0; nt2 < 4; nt2++) {
                uint32_t row = wn * 64 + nt2 * 16 + (lane & 15);
                uint32_t r0, r1, r2, r3;
                ldmx4(bbse + row * 128 + kx, r0, r1, r2, r3);
                bb[nt2 * 2][0] = r0; bb[nt2 * 2][1] = r2;
                bb[nt2 * 2 + 1][0] = r1; bb[nt2 * 2 + 1][1] = r3;
            }
            #pragma unroll
            for (int mt = 0; mt < 2; mt++)
                #pragma unroll
                for (int nt = 0; nt < 8; nt++)
                    mma16816(acc[mt][nt], a[mt], bb[nt]);
        }
        __syncthreads();
    }

    // epilogue: per-row top-2 of dist = en2 - 2*dot within this 128-col tile
    #pragma unroll
    for (int mt = 0; mt < 2; mt++) {
        #pragma unroll
        for (int half = 0; half < 2; half++) {
            u64 t1 = ~0ull, t2 = ~0ull;
            #pragma unroll
            for (int nt = 0; nt < 8; nt++) {
                #pragma unroll
                for (int cc = 0; cc < 2; cc++) {
                    int col = wn * 64 + nt * 8 + (lane & 3) * 2 + cc;
                    float dist = fmaf(-2.0f, acc[mt][nt][half * 2 + cc], sEn[col]);
                    u64 pk = packdi(dist, n0 + col);
                    if (pk < t1) { t2 = t1; t1 = pk; }
                    else if (pk < t2) { t2 = pk; }
                }
            }
            #pragma unroll
            for (int dlt = 1; dlt <= 2; dlt <<= 1) {
                u64 o1 = __shfl_xor_sync(0xffffffffu, t1, dlt);
                u64 o2 = __shfl_xor_sync(0xffffffffu, t2, dlt);
                u64 n1 = min(t1, o1);
                u64 n2 = min(max(t1, o1), min(t2, o2));
                t1 = n1; t2 = n2;
            }
            if ((lane & 3) == 0) {
                int rl = wm * 32 + mt * 16 + half * 8 + (lane >> 2);
                sPart[rl * 4 + wn * 2] = t1;
                sPart[rl * 4 + wn * 2 + 1] = t2;
            }
        }
    }
    __syncthreads();
    if (tid < 128) {
        u64 a1 = sPart[tid * 4], a2 = sPart[tid * 4 + 1];
        u64 b1 = sPart[tid * 4 + 2], b2 = sPart[tid * 4 + 3];
        u64 n1 = min(a1, b1);
        u64 n2 = min(max(a1, b1), min(a2, b2));
        g_part[(size_t)(m0 + tid) * 128 + ntile * 2] = n1;
        g_part[(size_t)(m0 + tid) * 128 + ntile * 2 + 1] = n2;
    }
}

// ---------------- merge + exact recheck (fast path + lane-parallel fulls) ----------
__device__ __forceinline__ u64 exact_pk(const float* __restrict__ E,
                                        const float xv[8], int lane, int k) {
    const float* ek = E + (size_t)k * D;
    float s = 0.0f;
    #pragma unroll
    for (int j = 0; j < 8; j++) s = fmaf(xv[j], __ldg(ek + lane + j * 32), s);
    #pragma unroll
    for (int o = 16; o > 0; o >>= 1) s += __shfl_xor_sync(0xffffffffu, s, o);
    float dist = fmaf(-2.0f, s, __ldg(&g_en2[k]));
    return packdi(dist, k);
}

__global__ void merge_kernel(const float* __restrict__ E, float* __restrict__ out) {
    __shared__ float sx[8][256];
    int wid = threadIdx.x >> 5, lane = threadIdx.x & 31;
    int row = blockIdx.x * 8 + wid;
    const float* xr = g_Axf + (size_t)row * D;
    float xv[8];
    #pragma unroll
    for (int j = 0; j < 8; j++) {
        xv[j] = __ldg(xr + lane + j * 32);           // coalesced
        sx[wid][lane + j * 32] = xv[j];
    }
    __syncwarp();

    u64 e[4];
    #pragma unroll
    for (int j = 0; j < 4; j++) e[j] = g_part[(size_t)row * 128 + lane * 4 + j];

    u64 m = min(min(e[0], e[1]), min(e[2], e[3]));
    #pragma unroll
    for (int o = 16; o > 0; o >>= 1) m = min(m, __shfl_xor_sync(0xffffffffu, m, o));
    // rigorous fp16 error pad: 2*E_max = 2^-9 * max||x|| * max||e|| (~0.69); use 0.93
    float pad = 0.0025f * sqrtf(__int_as_float(g_maxxn))
                        * sqrtf(__int_as_float(g_maxen)) + 0.05f;
    float thr = unpackd(m) + pad;

    bool full0 = unpackd(e[1]) <= thr;
    bool sing0 = (!full0) && (unpackd(e[0]) <= thr);
    bool full1 = unpackd(e[3]) <= thr;
    bool sing1 = (!full1) && (unpackd(e[2]) <= thr);
    unsigned mf0 = __ballot_sync(0xffffffffu, full0);
    unsigned ms0 = __ballot_sync(0xffffffffu, sing0);
    unsigned mf1 = __ballot_sync(0xffffffffu, full1);
    unsigned ms1 = __ballot_sync(0xffffffffu, sing1);

    // fast path: a single candidate -> approx argmin is exact argmin
    if ((mf0 | mf1) == 0 && __popc(ms0) + __popc(ms1) == 1) {
        if (lane == 0) {
            int k = (int)(m & 0xFFFFFFFFu);
            g_idx[row] = k;
            out[IDX_OFF + row] = (float)k;
        }
        return;
    }

    u64 best = ~0ull;
    int my0 = (int)(e[0] & 0xFFFFFFFFu), my1 = (int)(e[2] & 0xFFFFFFFFu);
    while (ms0) {
        int s = __ffs(ms0) - 1; ms0 &= ms0 - 1;
        int k = __shfl_sync(0xffffffffu, my0, s);
        best = min(best, exact_pk(E, xv, lane, k));
    }
    while (ms1) {
        int s = __ffs(ms1) - 1; ms1 &= ms1 - 1;
        int k = __shfl_sync(0xffffffffu, my1, s);
        best = min(best, exact_pk(E, xv, lane, k));
    }

    // lane-parallel full-tile rechecks: 32 codes at a time
    const float4* sx4 = (const float4*)sx[wid];
    while (mf0 | mf1) {
        int t, s;
        if (mf0) { s = __ffs(mf0) - 1; mf0 &= mf0 - 1; t = 0; }
        else     { s = __ffs(mf1) - 1; mf1 &= mf1 - 1; t = 1; }
        int k0 = (s * 2 + t) * 128;
        for (int bs = 0; bs < 128; bs += 32) {
            int k = k0 + bs + lane;
            const float4* ek = (const float4*)(E + (size_t)k * D);
            float a0 = 0.f, a1 = 0.f, a2 = 0.f, a3 = 0.f;
            #pragma unroll
            for (int q = 0; q < 64; q += 4) {
                float4 ea = __ldg(ek + q),     eb = __ldg(ek + q + 1);
                float4 ec = __ldg(ek + q + 2), ed = __ldg(ek + q + 3);
                float4 xa = sx4[q],     xb = sx4[q + 1];
                float4 xc = sx4[q + 2], xd = sx4[q + 3];
                a0 = fmaf(xa.x, ea.x, fmaf(xa.y, ea.y, fmaf(xa.z, ea.z, fmaf(xa.w, ea.w, a0))));
                a1 = fmaf(xb.x, eb.x, fmaf(xb.y, eb.y, fmaf(xb.z, eb.z, fmaf(xb.w, eb.w, a1))));
                a2 = fmaf(xc.x, ec.x, fmaf(xc.y, ec.y, fmaf(xc.z, ec.z, fmaf(xc.w, ec.w, a2))));
                a3 = fmaf(xd.x, ed.x, fmaf(xd.y, ed.y, fmaf(xd.z, ed.z, fmaf(xd.w, ed.w, a3))));
            }
            float dot = (a0 + a1) + (a2 + a3);
            float dist = fmaf(-2.0f, dot, __ldg(&g_en2[k]));
            best = min(best, packdi(dist, k));
        }
    }

    #pragma unroll
    for (int o = 16; o > 0; o >>= 1) best = min(best, __shfl_xor_sync(0xffffffffu, best, o));
    if (lane == 0) {
        int k = (int)(best & 0xFFFFFFFFu);
        g_idx[row] = k;
        out[IDX_OFF + row] = (float)k;
    }
}

// ---------------- final gather + loss ----------------
__global__ void final_kernel(const float* __restrict__ hs,
                             const float* __restrict__ E,
                             float* __restrict__ out) {
    __shared__ int sIdx[128];
    __shared__ float sRed[8];
    int tid = threadIdx.x;
    int row0 = blockIdx.x * 128;
    int b = row0 >> 10, p0 = row0 & 1023;
    size_t xbase = (size_t)b * 256 * 1024 + p0;

    if (tid < 128) sIdx[tid] = g_idx[row0 + tid];
    __syncthreads();

    float lsum = 0.0f;
    #pragma unroll 4
    for (int i = 0; i < 128; i++) {
        int lin = i * 256 + tid;
        int c = lin >> 7, r = lin & 127;
        int k = sIdx[r];
        float ev = __ldg(E + (size_t)k * D + c);
        size_t ad = xbase + (size_t)c * 1024 + r;
        float xv = hs[ad];
        out[ad] = ev;
        float dlt = ev - xv;
        lsum = fmaf(dlt, dlt, lsum);
    }
    #pragma unroll
    for (int o = 16; o > 0; o >>= 1) lsum += __shfl_xor_sync(0xffffffffu, lsum, o);
    if ((tid & 31) == 0) sRed[tid >> 5] = lsum;
    __syncthreads();
    if (tid == 0) {
        float tot = 0.0f;
        #pragma unroll
        for (int w = 0; w < 8; w++) tot += sRed[w];
        atomicAdd(out + LOSS_OFF, tot * (1.25f / 4194304.0f));
    }
}

extern "C" void kernel_launch(void* const* d_in, const int* in_sizes, int n_in,
                              void* d_out, int out_size) {
    const float* hs = (const float*)d_in[0];
    const float* E  = (const float*)d_in[1];
    float* out = (float*)d_out;

    cudaFuncSetAttribute(gemm_kernel,
                         cudaFuncAttributeMaxDynamicSharedMemorySize, SMEM_SZ);

    prepE_kernel<<<KC / 8, 256>>>(E, out);
    prepA_kernel<<<N_ROWS / 32, dim3(32, 8)>>>(hs);
    gemm_kernel<<<dim3(KC / 128, N_ROWS / 128), 256, SMEM_SZ>>>();
    merge_kernel<<<N_ROWS / 8, 256>>>(E, out);
    final_kernel<<<N_ROWS / 128, 256>>>(hs, E, out);
}

// round 7
// speedup vs baseline: 1.7196x; 1.0917x over previous
#include <cuda_runtime.h>
#include <cuda_fp16.h>
#include <cstdint>

// ---------------- problem constants ----------------
#define N_ROWS 16384
#define KC 8192
#define D 256
#define LOSS_OFF 4194304
#define IDX_OFF 4194305

typedef unsigned long long u64;

// ---------------- device scratch ----------------
__device__ __half g_Ah[(size_t)N_ROWS * D];   // x fp16 [m][k]
__device__ __half g_Bh[(size_t)KC * D];       // e fp16 [n][k]
__device__ float g_Axf[(size_t)N_ROWS * D];   // x fp32 row-major (exact recheck)
__device__ float g_en2[KC];                   // ||e||^2 fp32
__device__ float g_xn2[N_ROWS];               // ||x||^2 per row
__device__ int g_maxen = 0;                   // max ||e||^2 bits (atomicMax, idempotent)
__device__ u64 g_part[(size_t)N_ROWS * 128];  // per row: 64 tiles x top-2
__device__ int g_idx[N_ROWS];

// ---------------- helpers ----------------
__device__ __forceinline__ uint32_t smem_u32(const void* p) {
    uint32_t a;
    asm("{ .reg .u64 t; cvta.to.shared.u64 t, %1; cvt.u32.u64 %0, t; }" : "=r"(a) : "l"(p));
    return a;
}
__device__ __forceinline__ u64 packdi(float d, int idx) {
    uint32_t u = __float_as_uint(d);
    u = (u & 0x80000000u) ? ~u : (u | 0x80000000u);
    return ((u64)u << 32) | (uint32_t)idx;
}
__device__ __forceinline__ float unpackd(u64 p) {
    uint32_t u = (uint32_t)(p >> 32);
    u = (u & 0x80000000u) ? (u ^ 0x80000000u) : ~u;
    return __uint_as_float(u);
}
__device__ __forceinline__ void cpasync16(uint32_t sdst, const void* gsrc) {
    asm volatile("cp.async.cg.shared.global [%0], [%1], 16;" :: "r"(sdst), "l"(gsrc));
}
__device__ __forceinline__ void ldmx4(uint32_t addr, uint32_t& r0, uint32_t& r1,
                                      uint32_t& r2, uint32_t& r3) {
    asm volatile("ldmatrix.sync.aligned.m8n8.x4.shared.b16 {%0,%1,%2,%3}, [%4];"
                 : "=r"(r0), "=r"(r1), "=r"(r2), "=r"(r3) : "r"(addr));
}
__device__ __forceinline__ void mma16816(float* c, const uint32_t* a, const uint32_t* b) {
    asm volatile(
        "mma.sync.aligned.m16n8k16.row.col.f32.f16.f16.f32 "
        "{%0,%1,%2,%3}, {%4,%5,%6,%7}, {%8,%9}, {%0,%1,%2,%3};"
        : "+f"(c[0]), "+f"(c[1]), "+f"(c[2]), "+f"(c[3])
        : "r"(a[0]), "r"(a[1]), "r"(a[2]), "r"(a[3]), "r"(b[0]), "r"(b[1]));
}

// ---------------- prepE: E -> fp16 + ||e||^2 + max norm + loss init ----------------
__global__ void prepE_kernel(const float* __restrict__ E, float* out) {
    int k = blockIdx.x * 8 + (threadIdx.x >> 5);
    int lane = threadIdx.x & 31;
    if (blockIdx.x == 0 && threadIdx.x == 0) out[LOSS_OFF] = 0.0f;
    const float4* p = (const float4*)(E + (size_t)k * D);
    float4 v0 = p[lane * 2], v1 = p[lane * 2 + 1];
    __half2 h0 = __floats2half2_rn(v0.x, v0.y), h1 = __floats2half2_rn(v0.z, v0.w);
    __half2 h2 = __floats2half2_rn(v1.x, v1.y), h3 = __floats2half2_rn(v1.z, v1.w);
    uint4 o;
    o.x = *(uint32_t*)&h0; o.y = *(uint32_t*)&h1;
    o.z = *(uint32_t*)&h2; o.w = *(uint32_t*)&h3;
    *(uint4*)(g_Bh + (size_t)k * D + lane * 8) = o;
    float s = v0.x*v0.x + v0.y*v0.y + v0.z*v0.z + v0.w*v0.w
            + v1.x*v1.x + v1.y*v1.y + v1.z*v1.z + v1.w*v1.w;
    #pragma unroll
    for (int off = 16; off > 0; off >>= 1) s += __shfl_xor_sync(0xffffffffu, s, off);
    if (lane == 0) {
        g_en2[k] = s;
        atomicMax(&g_maxen, __float_as_int(s));
    }
}

// ---------------- prepA: hs -> g_Ah fp16 + g_Axf fp32 (transposed), row norms ------
__global__ void prepA_kernel(const float* __restrict__ hs) {
    __shared__ float tile[32][33];
    __shared__ float snorm[8][32];
    int m0 = blockIdx.x * 32, b = m0 >> 10, p0 = m0 & 1023;
    int tx = threadIdx.x, ty = threadIdx.y;   // 32 x 8
    float nacc = 0.0f;
    for (int cc = 0; cc < 8; cc++) {
        int c0 = cc * 32;
        __syncthreads();
        #pragma unroll
        for (int i = 0; i < 4; i++) {
            int c = c0 + ty + i * 8;
            float v = hs[((size_t)(b * 256 + c)) * 1024 + p0 + tx];
            tile[ty + i * 8][tx] = v;
            nacc = fmaf(v, v, nacc);
        }
        __syncthreads();
        #pragma unroll
        for (int i = 0; i < 4; i++) {
            int row = ty + i * 8;
            float v = tile[tx][row];
            g_Ah[(size_t)(m0 + row) * D + c0 + tx] = __float2half_rn(v);
            g_Axf[(size_t)(m0 + row) * D + c0 + tx] = v;
        }
    }
    snorm[ty][tx] = nacc;
    __syncthreads();
    if (ty == 0) {
        float tot = 0.0f;
        #pragma unroll
        for (int j = 0; j < 8; j++) tot += snorm[j][tx];
        g_xn2[m0 + tx] = tot;                 // per-row norm for merge pad
    }
}

// ---------------- main GEMM (fp16 mma.sync), CTA 128x128, 2-stage ------------------
#define SA_OFF(b) ((b) * 16384)
#define SB_OFF(b) (32768 + (b) * 16384)
#define SEN_OFF   65536
#define SPART_OFF 66048
#define SMEM_SZ   (1024 + 66048 + 4096)

__global__ void __launch_bounds__(256, 2)
gemm_kernel() {
    extern __shared__ char smem_raw[];
    char* base = (char*)(((uintptr_t)smem_raw + 1023) & ~(uintptr_t)1023);
    uint32_t sb = smem_u32(base);
    float* sEn = (float*)(base + SEN_OFF);
    u64* sPart = (u64*)(base + SPART_OFF);

    const int tid = threadIdx.x;
    const int lane = tid & 31, wid = tid >> 5;
    const int wm = wid & 3, wn = wid >> 2;
    const int ntile = blockIdx.x, mtile = blockIdx.y;
    const int m0 = mtile * 128, n0 = ntile * 128;

    if (tid < 128) sEn[tid] = g_en2[n0 + tid];

    auto load_chunk = [&](int c, int bf) {
        #pragma unroll
        for (int it = 0; it < 4; it++) {
            int idx = tid + it * 256;
            int row = idx >> 3, kg = idx & 7;
            uint32_t soff = row * 128 + (((uint32_t)(kg ^ (row & 7))) << 4);
            cpasync16(sb + SA_OFF(bf) + soff,
                      g_Ah + (size_t)(m0 + row) * D + c * 64 + kg * 8);
            cpasync16(sb + SB_OFF(bf) + soff,
                      g_Bh + (size_t)(n0 + row) * D + c * 64 + kg * 8);
        }
        asm volatile("cp.async.commit_group;");
    };

    float acc[2][8][4];
    #pragma unroll
    for (int mt = 0; mt < 2; mt++)
        #pragma unroll
        for (int nt = 0; nt < 8; nt++)
            #pragma unroll
            for (int q = 0; q < 4; q++) acc[mt][nt][q] = 0.0f;

    load_chunk(0, 0);

    for (int c = 0; c < 4; c++) {
        if (c + 1 < 4) {
            load_chunk(c + 1, (c + 1) & 1);
            asm volatile("cp.async.wait_group 1;" ::: "memory");
        } else {
            asm volatile("cp.async.wait_group 0;" ::: "memory");
        }
        __syncthreads();
        uint32_t ab = sb + SA_OFF(c & 1), bbse = sb + SB_OFF(c & 1);
        #pragma unroll
        for (int ks = 0; ks < 4; ks++) {
            uint32_t a[2][4], bb[8][2];
            uint32_t kg = ks * 2 + (lane >> 4);
            uint32_t kx = ((kg ^ (lane & 7)) << 4);
            #pragma unroll
            for (int mt = 0; mt < 2; mt++) {
                uint32_t row = wm * 32 + mt * 16 + (lane & 15);
                ldmx4(ab + row * 128 + kx, a[mt][0], a[mt][1], a[mt][2], a[mt][3]);
            }
            #pragma unroll
            for (int nt2 = 0; nt2 < 4; nt2++) {
                uint32_t row = wn * 64 + nt2 * 16 + (lane & 15);
                uint32_t r0, r1, r2, r3;
                ldmx4(bbse + row * 128 + kx, r0, r1, r2, r3);
                bb[nt2 * 2][0] = r0; bb[nt2 * 2][1] = r2;
                bb[nt2 * 2 + 1][0] = r1; bb[nt2 * 2 + 1][1] = r3;
            }
            #pragma unroll
            for (int mt = 0; mt < 2; mt++)
                #pragma unroll
                for (int nt = 0; nt < 8; nt++)
                    mma16816(acc[mt][nt], a[mt], bb[nt]);
        }
        __syncthreads();
    }

    // epilogue: per-row top-2 of dist = en2 - 2*dot within this 128-col tile
    #pragma unroll
    for (int mt = 0; mt < 2; mt++) {
        #pragma unroll
        for (int half = 0; half < 2; half++) {
            u64 t1 = ~0ull, t2 = ~0ull;
            #pragma unroll
            for (int nt = 0; nt < 8; nt++) {
                #pragma unroll
                for (int cc = 0; cc < 2; cc++) {
                    int col = wn * 64 + nt * 8 + (lane & 3) * 2 + cc;
                    float dist = fmaf(-2.0f, acc[mt][nt][half * 2 + cc], sEn[col]);
                    u64 pk = packdi(dist, n0 + col);
                    if (pk < t1) { t2 = t1; t1 = pk; }
                    else if (pk < t2) { t2 = pk; }
                }
            }
            #pragma unroll
            for (int dlt = 1; dlt <= 2; dlt <<= 1) {
                u64 o1 = __shfl_xor_sync(0xffffffffu, t1, dlt);
                u64 o2 = __shfl_xor_sync(0xffffffffu, t2, dlt);
                u64 n1 = min(t1, o1);
                u64 n2 = min(max(t1, o1), min(t2, o2));
                t1 = n1; t2 = n2;
            }
            if ((lane & 3) == 0) {
                int rl = wm * 32 + mt * 16 + half * 8 + (lane >> 2);
                sPart[rl * 4 + wn * 2] = t1;
                sPart[rl * 4 + wn * 2 + 1] = t2;
            }
        }
    }
    __syncthreads();
    if (tid < 128) {
        u64 a1 = sPart[tid * 4], a2 = sPart[tid * 4 + 1];
        u64 b1 = sPart[tid * 4 + 2], b2 = sPart[tid * 4 + 3];
        u64 n1 = min(a1, b1);
        u64 n2 = min(max(a1, b1), min(a2, b2));
        g_part[(size_t)(m0 + tid) * 128 + ntile * 2] = n1;
        g_part[(size_t)(m0 + tid) * 128 + ntile * 2 + 1] = n2;
    }
}

// ---------------- merge + exact recheck (deferred x-load) ---------------------------
__device__ __forceinline__ u64 exact_pk(const float* __restrict__ E,
                                        const float xv[8], int lane, int k) {
    const float* ek = E + (size_t)k * D;
    float s = 0.0f;
    #pragma unroll
    for (int j = 0; j < 8; j++) s = fmaf(xv[j], __ldg(ek + lane + j * 32), s);
    #pragma unroll
    for (int o = 16; o > 0; o >>= 1) s += __shfl_xor_sync(0xffffffffu, s, o);
    float dist = fmaf(-2.0f, s, __ldg(&g_en2[k]));
    return packdi(dist, k);
}

__global__ void merge_kernel(const float* __restrict__ E, float* __restrict__ out) {
    __shared__ float sx[8][256];
    int wid = threadIdx.x >> 5, lane = threadIdx.x & 31;
    int row = blockIdx.x * 8 + wid;

    u64 e[4];
    #pragma unroll
    for (int j = 0; j < 4; j++) e[j] = g_part[(size_t)row * 128 + lane * 4 + j];

    u64 m = min(min(e[0], e[1]), min(e[2], e[3]));
    #pragma unroll
    for (int o = 16; o > 0; o >>= 1) m = min(m, __shfl_xor_sync(0xffffffffu, m, o));

    // rigorous fp16 pad: 2*Emax = 2^-9 * ||x_row|| * max||e||  (+ slack)
    float pad = 0.00196f * sqrtf(__ldg(&g_xn2[row]) * __int_as_float(g_maxen)) + 0.05f;
    float thr = unpackd(m) + pad;

    bool full0 = unpackd(e[1]) <= thr;
    bool sing0 = (!full0) && (unpackd(e[0]) <= thr);
    bool full1 = unpackd(e[3]) <= thr;
    bool sing1 = (!full1) && (unpackd(e[2]) <= thr);
    unsigned mf0 = __ballot_sync(0xffffffffu, full0);
    unsigned ms0 = __ballot_sync(0xffffffffu, sing0);
    unsigned mf1 = __ballot_sync(0xffffffffu, full1);
    unsigned ms1 = __ballot_sync(0xffffffffu, sing1);

    // fast path (~89% of rows): single candidate -> approx argmin is exact argmin
    if ((mf0 | mf1) == 0 && __popc(ms0) + __popc(ms1) == 1) {
        if (lane == 0) {
            int k = (int)(m & 0xFFFFFFFFu);
            g_idx[row] = k;
            out[IDX_OFF + row] = (float)k;
        }
        return;
    }

    // slow path: load x row now (coalesced)
    const float* xr = g_Axf + (size_t)row * D;
    float xv[8];
    #pragma unroll
    for (int j = 0; j < 8; j++) xv[j] = __ldg(xr + lane + j * 32);

    u64 best = ~0ull;
    int my0 = (int)(e[0] & 0xFFFFFFFFu), my1 = (int)(e[2] & 0xFFFFFFFFu);
    {
        unsigned t0 = ms0;
        while (t0) {
            int s = __ffs(t0) - 1; t0 &= t0 - 1;
            int k = __shfl_sync(0xffffffffu, my0, s);
            best = min(best, exact_pk(E, xv, lane, k));
        }
        unsigned t1m = ms1;
        while (t1m) {
            int s = __ffs(t1m) - 1; t1m &= t1m - 1;
            int k = __shfl_sync(0xffffffffu, my1, s);
            best = min(best, exact_pk(E, xv, lane, k));
        }
    }

    if (mf0 | mf1) {
        // stage x to smem for lane-parallel full-tile rechecks
        #pragma unroll
        for (int j = 0; j < 8; j++) sx[wid][lane + j * 32] = xv[j];
        __syncwarp();
        const float4* sx4 = (const float4*)sx[wid];
        while (mf0 | mf1) {
            int t, s;
            if (mf0) { s = __ffs(mf0) - 1; mf0 &= mf0 - 1; t = 0; }
            else     { s = __ffs(mf1) - 1; mf1 &= mf1 - 1; t = 1; }
            int k0 = (s * 2 + t) * 128;
            for (int bs = 0; bs < 128; bs += 32) {
                int k = k0 + bs + lane;
                const float4* ek = (const float4*)(E + (size_t)k * D);
                float a0 = 0.f, a1 = 0.f, a2 = 0.f, a3 = 0.f;
                #pragma unroll
                for (int q = 0; q < 64; q += 4) {
                    float4 ea = __ldg(ek + q),     eb = __ldg(ek + q + 1);
                    float4 ec = __ldg(ek + q + 2), ed = __ldg(ek + q + 3);
                    float4 xa = sx4[q],     xb = sx4[q + 1];
                    float4 xc = sx4[q + 2], xd = sx4[q + 3];
                    a0 = fmaf(xa.x, ea.x, fmaf(xa.y, ea.y, fmaf(xa.z, ea.z, fmaf(xa.w, ea.w, a0))));
                    a1 = fmaf(xb.x, eb.x, fmaf(xb.y, eb.y, fmaf(xb.z, eb.z, fmaf(xb.w, eb.w, a1))));
                    a2 = fmaf(xc.x, ec.x, fmaf(xc.y, ec.y, fmaf(xc.z, ec.z, fmaf(xc.w, ec.w, a2))));
                    a3 = fmaf(xd.x, ed.x, fmaf(xd.y, ed.y, fmaf(xd.z, ed.z, fmaf(xd.w, ed.w, a3))));
                }
                float dot = (a0 + a1) + (a2 + a3);
                float dist = fmaf(-2.0f, dot, __ldg(&g_en2[k]));
                best = min(best, packdi(dist, k));
            }
        }
    }

    #pragma unroll
    for (int o = 16; o > 0; o >>= 1) best = min(best, __shfl_xor_sync(0xffffffffu, best, o));
    if (lane == 0) {
        int k = (int)(best & 0xFFFFFFFFu);
        g_idx[row] = k;
        out[IDX_OFF + row] = (float)k;
    }
}

// ---------------- final gather + loss (float4) --------------------------------------
__global__ void final_kernel(const float* __restrict__ hs,
                             const float* __restrict__ E,
                             float* __restrict__ out) {
    __shared__ int sIdx[128];
    __shared__ float sRed[8];
    int tid = threadIdx.x;
    int lane = tid & 31;
    int row0 = blockIdx.x * 128;
    int b = row0 >> 10, p0 = row0 & 1023;
    size_t xbase = (size_t)b * 256 * 1024 + p0;

    if (tid < 128) sIdx[tid] = g_idx[row0 + tid];
    __syncthreads();

    int k0 = sIdx[lane * 4], k1 = sIdx[lane * 4 + 1];
    int k2 = sIdx[lane * 4 + 2], k3 = sIdx[lane * 4 + 3];

    float lsum = 0.0f;
    #pragma unroll 4
    for (int i = 0; i < 32; i++) {
        int c = i * 8 + (tid >> 5);
        size_t ad = xbase + (size_t)c * 1024 + lane * 4;
        float4 xv = *(const float4*)(hs + ad);
        float4 ev;
        ev.x = __ldg(E + (size_t)k0 * D + c);
        ev.y = __ldg(E + (size_t)k1 * D + c);
        ev.z = __ldg(E + (size_t)k2 * D + c);
        ev.w = __ldg(E + (size_t)k3 * D + c);
        *(float4*)(out + ad) = ev;
        float d0 = ev.x - xv.x, d1 = ev.y - xv.y;
        float d2 = ev.z - xv.z, d3 = ev.w - xv.w;
        lsum = fmaf(d0, d0, lsum);
        lsum = fmaf(d1, d1, lsum);
        lsum = fmaf(d2, d2, lsum);
        lsum = fmaf(d3, d3, lsum);
    }
    #pragma unroll
    for (int o = 16; o > 0; o >>= 1) lsum += __shfl_xor_sync(0xffffffffu, lsum, o);
    if ((tid & 31) == 0) sRed[tid >> 5] = lsum;
    __syncthreads();
    if (tid == 0) {
        float tot = 0.0f;
        #pragma unroll
        for (int w = 0; w < 8; w++) tot += sRed[w];
        atomicAdd(out + LOSS_OFF, tot * (1.25f / 4194304.0f));
    }
}

extern "C" void kernel_launch(void* const* d_in, const int* in_sizes, int n_in,
                              void* d_out, int out_size) {
    const float* hs = (const float*)d_in[0];
    const float* E  = (const float*)d_in[1];
    float* out = (float*)d_out;

    cudaFuncSetAttribute(gemm_kernel,
                         cudaFuncAttributeMaxDynamicSharedMemorySize, SMEM_SZ);

    prepE_kernel<<<KC / 8, 256>>>(E, out);
    prepA_kernel<<<N_ROWS / 32, dim3(32, 8)>>>(hs);
    gemm_kernel<<<dim3(KC / 128, N_ROWS / 128), 256, SMEM_SZ>>>();
    merge_kernel<<<N_ROWS / 8, 256>>>(E, out);
    final_kernel<<<N_ROWS / 128, 256>>>(hs, E, out);
}